// round 1
// baseline (speedup 1.0000x reference)
#include <cuda_runtime.h>

// Conv2d: N=16, C=128, H=W=56, K=128, R=S=3, pad=1, stride=1, fp32.
// Direct conv, smem tiling: block = 64 K x 2 rows x 56 W for one image.
// Thread tile = 4k x 7w. C processed in chunks of 8.

#define CN 16
#define CC_ 128
#define CH 56
#define CW 56
#define CK 128

#define CCH 8      // c chunk
#define KT  64     // k per block
#define PT  2      // output rows per block
#define TW  7      // w per thread
#define TK  4      // k per thread

__global__ __launch_bounds__(256, 2)
void conv3x3_kernel(const float* __restrict__ in,
                    const float* __restrict__ wt,
                    const float* __restrict__ bias,
                    float* __restrict__ out)
{
    __shared__ float s_in[CCH][PT + 2][60];     // rows h0-1..h0+2, w padded -1..56 (58 used)
    __shared__ float s_wt[CCH * 9][68];         // [cc*9+rs][k], pad 68 to soften STS conflicts

    const int ktile = blockIdx.x;               // 0..1
    const int h0    = blockIdx.y * PT;          // 0..54
    const int n     = blockIdx.z;               // 0..15

    const int tid = threadIdx.x;
    const int twg = tid & 7;                    // w group 0..7
    const int tkg = (tid >> 3) & 15;            // k group 0..15
    const int th  = tid >> 7;                   // row within tile 0..1

    const int w0     = twg * TW;                // 0..49
    const int klocal = tkg * TK;                // 0..60
    const int kglob  = ktile * KT + klocal;

    float acc[TK][TW];
    #pragma unroll
    for (int j = 0; j < TK; j++)
        #pragma unroll
        for (int x = 0; x < TW; x++) acc[j][x] = 0.f;

    const float* in_n = in + (size_t)n * CC_ * CH * CW;

    for (int c0 = 0; c0 < CC_; c0 += CCH) {
        __syncthreads();

        // ---- load input tile: CCH * (PT+2) * 58 elements, coalesced rows ----
        for (int idx = tid; idx < CCH * (PT + 2) * 58; idx += 256) {
            int wl = idx % 58;
            int t  = idx / 58;
            int r  = t & 3;                     // PT+2 == 4
            int cc = t >> 2;
            int hin = h0 - 1 + r;
            int win = wl - 1;
            float v = 0.f;
            if ((unsigned)hin < CH && (unsigned)win < CW)
                v = in_n[((c0 + cc) * CH + hin) * CW + win];
            s_in[cc][r][wl] = v;
        }

        // ---- load weight tile: KT*CCH*9 = 4608 elems, coalesced global reads ----
        // idx = k*72 + rs72, rs72 = cc*9 + r*3 + s  (contiguous in gmem for fixed k)
        for (int idx = tid; idx < KT * CCH * 9; idx += 256) {
            int rs72 = idx % 72;
            int k    = idx / 72;
            s_wt[rs72][k] =
                wt[(size_t)(ktile * KT + k) * (CC_ * 9) + c0 * 9 + rs72];
        }

        __syncthreads();

        // ---- compute ----
        #pragma unroll 2
        for (int cc = 0; cc < CCH; cc++) {
            #pragma unroll
            for (int r = 0; r < 3; r++) {
                float inr[TW + 2];
                #pragma unroll
                for (int i = 0; i < TW + 2; i++)
                    inr[i] = s_in[cc][th + r][w0 + i];

                #pragma unroll
                for (int s = 0; s < 3; s++) {
                    const float* wrow = &s_wt[cc * 9 + r * 3 + s][klocal];
                    float wv[TK];
                    #pragma unroll
                    for (int j = 0; j < TK; j++) wv[j] = wrow[j];  // LDS.128

                    #pragma unroll
                    for (int j = 0; j < TK; j++)
                        #pragma unroll
                        for (int x = 0; x < TW; x++)
                            acc[j][x] += wv[j] * inr[x + s];
                }
            }
        }
    }

    // ---- epilogue: bias + store ----
    const int hout = h0 + th;
    float* out_n = out + (size_t)n * CK * CH * CW;
    #pragma unroll
    for (int j = 0; j < TK; j++) {
        float bv = bias[kglob + j];
        float* orow = out_n + (size_t)(kglob + j) * CH * CW + hout * CW + w0;
        #pragma unroll
        for (int x = 0; x < TW; x++)
            orow[x] = acc[j][x] + bv;
    }
}

extern "C" void kernel_launch(void* const* d_in, const int* in_sizes, int n_in,
                              void* d_out, int out_size)
{
    const float* input  = (const float*)d_in[0];
    const float* weight = (const float*)d_in[1];
    const float* bias   = (const float*)d_in[2];
    float* out = (float*)d_out;

    dim3 grid(CK / KT, CH / PT, CN);   // (2, 28, 16)
    conv3x3_kernel<<<grid, 256>>>(input, weight, bias, out);
}

// round 2
// speedup vs baseline: 1.0806x; 1.0806x over previous
#include <cuda_runtime.h>

// Conv2d: N=16, C=128, H=W=56, K=128, R=S=3, pad=1, stride=1, fp32.
// Direct conv, smem tiling: block = 64 K x 2 rows x 56 W for one image.
// Thread tile = 4k x 7w, computed as 2 packed f32x2 k-pairs via fma.rn.f32x2
// (SASS FFMA2, sm_100+ packed fp32 — 2 FMAs per instruction).

#define CN 16
#define CC_ 128
#define CH 56
#define CW 56
#define CK 128

#define CCH 8      // c chunk
#define KT  64     // k per block
#define PT  2      // output rows per block
#define TW  7      // w per thread
#define TK  4      // k per thread (= 2 f32x2 pairs)

typedef unsigned long long u64;

__device__ __forceinline__ void ffma2(u64& d, u64 a, u64 b) {
    // d = a * b + d  (packed 2x fp32)
    asm("fma.rn.f32x2 %0, %1, %2, %0;" : "+l"(d) : "l"(a), "l"(b));
}

__device__ __forceinline__ u64 pack2(float x) {
    u64 r;
    asm("mov.b64 %0, {%1, %1};" : "=l"(r) : "f"(x));
    return r;
}

__device__ __forceinline__ float2 unpack2(u64 v) {
    float2 f;
    asm("mov.b64 {%0, %1}, %2;" : "=f"(f.x), "=f"(f.y) : "l"(v));
    return f;
}

__global__ __launch_bounds__(256, 2)
void conv3x3_kernel(const float* __restrict__ in,
                    const float* __restrict__ wt,
                    const float* __restrict__ bias,
                    float* __restrict__ out)
{
    __shared__ float s_in[CCH][PT + 2][60];     // rows h0-1..h0+2, w padded -1..56 (58 used)
    __shared__ float s_wt[CCH * 9][68];         // [cc*9+rs][k]; row stride 272B (16B aligned)

    const int ktile = blockIdx.x;               // 0..1
    const int h0    = blockIdx.y * PT;          // 0..54
    const int n     = blockIdx.z;               // 0..15

    const int tid = threadIdx.x;
    const int twg = tid & 7;                    // w group 0..7
    const int tkg = (tid >> 3) & 15;            // k group 0..15
    const int th  = tid >> 7;                   // row within tile 0..1

    const int w0     = twg * TW;                // 0..49
    const int klocal = tkg * TK;                // 0..60 (16B aligned for LDS.128)
    const int kglob  = ktile * KT + klocal;

    // acc[p][x]: p = k-pair (k0k1 / k2k3), x = w. Each u64 is a packed f32x2.
    u64 acc[2][TW];
    #pragma unroll
    for (int p = 0; p < 2; p++)
        #pragma unroll
        for (int x = 0; x < TW; x++) acc[p][x] = 0ull;

    const float* in_n = in + (size_t)n * CC_ * CH * CW;

    for (int c0 = 0; c0 < CC_; c0 += CCH) {
        __syncthreads();

        // ---- load input tile: CCH * (PT+2) * 58 elements, coalesced rows ----
        for (int idx = tid; idx < CCH * (PT + 2) * 58; idx += 256) {
            int wl = idx % 58;
            int t  = idx / 58;
            int r  = t & 3;                     // PT+2 == 4
            int cc = t >> 2;
            int hin = h0 - 1 + r;
            int win = wl - 1;
            float v = 0.f;
            if ((unsigned)hin < CH && (unsigned)win < CW)
                v = in_n[((c0 + cc) * CH + hin) * CW + win];
            s_in[cc][r][wl] = v;
        }

        // ---- load weight tile: KT*CCH*9 = 4608 elems, coalesced global reads ----
        for (int idx = tid; idx < KT * CCH * 9; idx += 256) {
            int rs72 = idx % 72;
            int k    = idx / 72;
            s_wt[rs72][k] =
                wt[(size_t)(ktile * KT + k) * (CC_ * 9) + c0 * 9 + rs72];
        }

        __syncthreads();

        // ---- compute ----
        #pragma unroll 2
        for (int cc = 0; cc < CCH; cc++) {
            #pragma unroll
            for (int r = 0; r < 3; r++) {
                // 9 input scalars for this row, duplicate-packed once
                u64 inp2[TW + 2];
                #pragma unroll
                for (int i = 0; i < TW + 2; i++)
                    inp2[i] = pack2(s_in[cc][th + r][w0 + i]);

                #pragma unroll
                for (int s = 0; s < 3; s++) {
                    // one LDS.128: 4 consecutive k-weights -> two f32x2 pairs
                    union { float4 v; u64 u[2]; } w;
                    w.v = *reinterpret_cast<const float4*>(
                              &s_wt[cc * 9 + r * 3 + s][klocal]);

                    #pragma unroll
                    for (int p = 0; p < 2; p++)
                        #pragma unroll
                        for (int x = 0; x < TW; x++)
                            ffma2(acc[p][x], w.u[p], inp2[x + s]);
                }
            }
        }
    }

    // ---- epilogue: bias + store ----
    const int hout = h0 + th;
    float* out_n = out + (size_t)n * CK * CH * CW;
    #pragma unroll
    for (int p = 0; p < 2; p++) {
        float b0 = bias[kglob + 2 * p + 0];
        float b1 = bias[kglob + 2 * p + 1];
        float* orow0 = out_n + (size_t)(kglob + 2 * p + 0) * CH * CW + hout * CW + w0;
        float* orow1 = out_n + (size_t)(kglob + 2 * p + 1) * CH * CW + hout * CW + w0;
        #pragma unroll
        for (int x = 0; x < TW; x++) {
            float2 v = unpack2(acc[p][x]);
            orow0[x] = v.x + b0;
            orow1[x] = v.y + b1;
        }
    }
}

extern "C" void kernel_launch(void* const* d_in, const int* in_sizes, int n_in,
                              void* d_out, int out_size)
{
    const float* input  = (const float*)d_in[0];
    const float* weight = (const float*)d_in[1];
    const float* bias   = (const float*)d_in[2];
    float* out = (float*)d_out;

    dim3 grid(CK / KT, CH / PT, CN);   // (2, 28, 16)
    conv3x3_kernel<<<grid, 256>>>(input, weight, bias, out);
}

// round 4
// speedup vs baseline: 3.6989x; 3.4230x over previous
#include <cuda_runtime.h>
#include <cstdint>

// Conv2d N=16,C=128,H=W=56,K=128,3x3,pad1 as 9 shifted GEMMs using
// mma.sync.m16n8k8 tf32 (base PTX, runs on Blackwell fallback HMMA).
// CTA = 128 k x 112 pos (2 rows x 56 w) of one image; 8 warps (4m x 2row).
// X tile per 32-c chunk covers 4 rows x 58 w; 3x3 shifts = address math.
// W pre-transposed/tf32-rounded by prep kernel, streamed via cp.async.

typedef uint32_t u32;

#define SX_ELEMS (32 * 232)          // 32 c x (4*58) padded to 232
#define SW_STAGE (128 * 36)          // [128 k][36 pad] u32
#define SW_OFF   SX_ELEMS
#define SMEM_BYTES ((SX_ELEMS + 2 * SW_STAGE) * 4)   // 66560

__device__ u32 g_Wt[36 * 4096];      // [cg*9+rs][k][c32], tf32 bits

__device__ __forceinline__ u32 f2tf(float f) {
    u32 r; asm("cvt.rna.tf32.f32 %0, %1;" : "=r"(r) : "f"(f)); return r;
}

__global__ void prep_weights(const float* __restrict__ wt) {
    int idx = blockIdx.x * 256 + threadIdx.x;
    if (idx >= 36 * 4096) return;
    int slab = idx >> 12;
    int k = (idx >> 5) & 127;
    int c = idx & 31;
    int cg = slab / 9, rs = slab % 9;
    g_Wt[idx] = f2tf(wt[(size_t)k * 1152 + (size_t)(cg * 32 + c) * 9 + rs]);
}

__global__ __launch_bounds__(256, 2)
void conv_mma(const float* __restrict__ in,
              const float* __restrict__ bias,
              float* __restrict__ out)
{
    extern __shared__ u32 sm[];
    u32* sX = sm;
    u32* sW = sm + SW_OFF;

    u32 sbase;
    asm("{ .reg .u64 t; cvta.to.shared.u64 t, %1; cvt.u32.u64 %0, t; }"
        : "=r"(sbase) : "l"(sm));
    const u32 swbase = sbase + SW_OFF * 4;

    const int tid = threadIdx.x;
    const int wid = tid >> 5, lid = tid & 31;
    const int lq = lid & 3, g = lid >> 2;
    const int m0 = (wid & 3) * 32;        // warp m offset (k channels)
    const int wn = wid >> 2;              // warp output row (0/1)

    const int img = blockIdx.x / 28;
    const int h0  = (blockIdx.x % 28) * 2;
    const float* in_n = in + (size_t)img * 401408;

    float acc[2][7][4];
    #pragma unroll
    for (int mt = 0; mt < 2; mt++)
        #pragma unroll
        for (int nt = 0; nt < 7; nt++)
            #pragma unroll
            for (int q = 0; q < 4; q++) acc[mt][nt][q] = 0.f;

    auto loadX = [&](int cg) {
        for (int idx = tid; idx < 32 * 4 * 58; idx += 256) {
            int wl = idx % 58;
            int t = idx / 58;
            int row = t & 3;
            int c = t >> 2;
            int hin = h0 - 1 + row;
            int win = wl - 1;
            float v = 0.f;
            if ((unsigned)hin < 56u && (unsigned)win < 56u)
                v = in_n[(size_t)(cg * 32 + c) * 3136 + hin * 56 + win];
            sX[c * 232 + row * 58 + wl] = f2tf(v);
        }
    };

    auto prefW = [&](int s, int buf) {
        const u32* src = g_Wt + (size_t)s * 4096;
        u32 dstb = swbase + buf * (SW_STAGE * 4);
        #pragma unroll
        for (int j = 0; j < 4; j++) {
            int chunk = tid + j * 256;
            int k = chunk >> 3, cq = chunk & 7;
            u32 dst = dstb + k * 144 + cq * 16;
            asm volatile("cp.async.ca.shared.global [%0], [%1], 16;"
                         :: "r"(dst), "l"(src + chunk * 4) : "memory");
        }
        asm volatile("cp.async.commit_group;" ::: "memory");
    };

    loadX(0);
    prefW(0, 0);
    __syncthreads();

    for (int s = 0; s < 36; s++) {
        const int buf = s & 1;
        if (s + 1 < 36) {
            prefW(s + 1, buf ^ 1);
            asm volatile("cp.async.wait_group 1;" ::: "memory");
        } else {
            asm volatile("cp.async.wait_group 0;" ::: "memory");
        }
        __syncthreads();   // W(s) + (re)loaded X visible to all

        const int rs = s % 9;
        const u32* Wb = sW + buf * SW_STAGE + (m0 + g) * 36 + lq;
        const u32* Bb = sX + lq * 232 + (wn + rs / 3) * 58 + g + (rs % 3);

        #pragma unroll
        for (int kk = 0; kk < 4; kk++) {
            u32 a[2][4], b[7][2];
            #pragma unroll
            for (int mt = 0; mt < 2; mt++) {
                const u32* p = Wb + mt * 576 + kk * 8;
                a[mt][0] = p[0];   a[mt][1] = p[288];
                a[mt][2] = p[4];   a[mt][3] = p[292];
            }
            #pragma unroll
            for (int nt = 0; nt < 7; nt++) {
                const u32* p = Bb + kk * 1856 + nt * 8;
                b[nt][0] = p[0];   b[nt][1] = p[928];
            }
            #pragma unroll
            for (int mt = 0; mt < 2; mt++)
                #pragma unroll
                for (int nt = 0; nt < 7; nt++)
                    asm volatile(
                        "mma.sync.aligned.m16n8k8.row.col.f32.tf32.tf32.f32 "
                        "{%0,%1,%2,%3}, {%4,%5,%6,%7}, {%8,%9}, {%0,%1,%2,%3};"
                        : "+f"(acc[mt][nt][0]), "+f"(acc[mt][nt][1]),
                          "+f"(acc[mt][nt][2]), "+f"(acc[mt][nt][3])
                        : "r"(a[mt][0]), "r"(a[mt][1]), "r"(a[mt][2]), "r"(a[mt][3]),
                          "r"(b[nt][0]), "r"(b[nt][1]));
        }
        __syncthreads();   // done reading W(buf)/X before they are overwritten
        if (rs == 8 && s + 1 < 36) loadX((s + 1) / 9);
    }

    // ---- epilogue: direct STG.64 + bias ----
    #pragma unroll
    for (int mt = 0; mt < 2; mt++)
        #pragma unroll
        for (int h = 0; h < 2; h++) {
            const int k = m0 + mt * 16 + h * 8 + g;
            const float bv = __ldg(&bias[k]);
            float* op = out + (size_t)img * 401408 + (size_t)k * 3136
                        + (h0 + wn) * 56 + lq * 2;
            #pragma unroll
            for (int nt = 0; nt < 7; nt++) {
                float2 v;
                v.x = acc[mt][nt][2 * h + 0] + bv;
                v.y = acc[mt][nt][2 * h + 1] + bv;
                *reinterpret_cast<float2*>(op + nt * 8) = v;
            }
        }
}

extern "C" void kernel_launch(void* const* d_in, const int* in_sizes, int n_in,
                              void* d_out, int out_size)
{
    const float* input  = (const float*)d_in[0];
    const float* weight = (const float*)d_in[1];
    const float* bias   = (const float*)d_in[2];
    float* out = (float*)d_out;

    cudaFuncSetAttribute(conv_mma, cudaFuncAttributeMaxDynamicSharedMemorySize,
                         SMEM_BYTES);

    prep_weights<<<(36 * 4096 + 255) / 256, 256>>>(weight);
    conv_mma<<<448, 256, SMEM_BYTES>>>(input, bias, out);
}